// round 7
// baseline (speedup 1.0000x reference)
#include <cuda_runtime.h>
#include <cuda_fp16.h>
#include <math.h>
#include <stdint.h>

#define SEQ 8192
#define DIM 768
#define DIM3 (3 * DIM)   // 2304

// ---------------- scratch (__device__ globals; no allocations allowed) -----
__device__ __align__(128) __half g_X16 [(size_t)SEQ * DIM];
__device__ __align__(128) __half g_Wc16[(size_t)DIM3 * DIM];       // [Wq;Wk;Wv]
__device__ __align__(128) __half g_QKV [(size_t)SEQ * DIM3];       // packed Q|K|V
__device__ __align__(128) __half g_V16t[(size_t)DIM * SEQ];
__device__ __align__(128) float  g_S   [(size_t)SEQ * SEQ];
__device__ __align__(128) __half g_P16 [(size_t)SEQ * SEQ];
__device__ __align__(128) float  g_Opart[4][(size_t)SEQ * DIM];    // PV split-K partials

// ---------------- helpers ----------------------------------------------------
__device__ __forceinline__ uint32_t smem_u32(const void* p) {
    uint32_t a;
    asm("{ .reg .u64 t; cvta.to.shared.u64 t, %1; cvt.u32.u64 %0, t; }"
        : "=r"(a) : "l"(p));
    return a;
}

#define MMA16816(d, a, b0, b1)                                                 \
    asm volatile(                                                              \
        "mma.sync.aligned.m16n8k16.row.col.f32.f16.f16.f32 "                   \
        "{%0,%1,%2,%3}, {%4,%5,%6,%7}, {%8,%9}, {%0,%1,%2,%3};"                \
        : "+f"((d)[0]), "+f"((d)[1]), "+f"((d)[2]), "+f"((d)[3])               \
        : "r"((a)[0]), "r"((a)[1]), "r"((a)[2]), "r"((a)[3]),                  \
          "r"(b0), "r"(b1))

#define LDSM_X4(r, addr)                                                       \
    asm volatile("ldmatrix.sync.aligned.m8n8.x4.shared.b16 {%0,%1,%2,%3}, [%4];" \
        : "=r"((r)[0]), "=r"((r)[1]), "=r"((r)[2]), "=r"((r)[3]) : "r"(addr))

#define CP_ASYNC16(saddr, gptr)                                                \
    asm volatile("cp.async.cg.shared.global [%0], [%1], 16;"                   \
        :: "r"(saddr), "l"(gptr))

// ---------------- GEMM: C[M,N] = alpha * A[M,*] * B[N,*]^T  (fp16 in)
// CTA tile 128x256, BK=64 halves, 8 warps each 64x64, 3-stage cp.async.
// Explicit row strides lda/ldb/ldc (elements). gridDim.z = K-splits: split z
// covers K range [z*Ke, (z+1)*Ke) and writes C + z*csplit.
// OUT_HALF: 0 -> fp32 C, 1 -> fp16 C.
#define BM 128
#define BN 256
#define BKH 64                     // halves per K tile (128 bytes per row)
#define A_BYTES (BM * 128)         // 16 KB per A stage
#define B_BYTES (BN * 128)         // 32 KB per B stage
#define NSTAGE 3
#define GEMM_SMEM (NSTAGE * (A_BYTES + B_BYTES))   // 144 KB

template <int OUT_HALF>
__global__ void __launch_bounds__(256, 1)
gemm_f16_mma(const __half* __restrict__ A, const __half* __restrict__ B,
             void* __restrict__ Cv, int N, int Ke,
             int lda, int ldb, int ldc, float alpha, size_t csplit)
{
    extern __shared__ char smem[];
    const uint32_t sA = smem_u32(smem);                 // NSTAGE stages A
    const uint32_t sB = sA + NSTAGE * A_BYTES;          // NSTAGE stages B

    const int tid  = threadIdx.x;
    const int lane = tid & 31;
    const int wid  = tid >> 5;
    const int warp_m = (wid & 1) * 64;      // 2 warps along M
    const int warp_n = (wid >> 1) * 64;     // 4 warps along N
    const int bm = blockIdx.y * BM;
    const int bn = blockIdx.x * BN;
    const int koff = blockIdx.z * Ke;
    const int nk = Ke / BKH;

    float acc[4][8][4];
#pragma unroll
    for (int i = 0; i < 4; ++i)
#pragma unroll
        for (int j = 0; j < 8; ++j)
#pragma unroll
            for (int k = 0; k < 4; ++k) acc[i][j][k] = 0.f;

#define LOAD_STAGE(kt, st)                                                     \
    do {                                                                       \
        _Pragma("unroll")                                                      \
        for (int i = 0; i < 4; ++i) {                                          \
            int idx = tid + i * 256;  /* 0..1023 : A chunks */                 \
            int row = idx >> 3;                                                \
            int ch  = idx & 7;                                                 \
            int pch = ch ^ (row & 7);                                          \
            const __half* gA = A + (size_t)(bm + row) * lda + koff + (kt) * BKH + ch * 8; \
            CP_ASYNC16(sA + (st) * A_BYTES + row * 128 + pch * 16, gA);        \
        }                                                                      \
        _Pragma("unroll")                                                      \
        for (int i = 0; i < 8; ++i) {                                          \
            int idx = tid + i * 256;  /* 0..2047 : B chunks */                 \
            int row = idx >> 3;                                                \
            int ch  = idx & 7;                                                 \
            int pch = ch ^ (row & 7);                                          \
            const __half* gB = B + (size_t)(bn + row) * ldb + koff + (kt) * BKH + ch * 8; \
            CP_ASYNC16(sB + (st) * B_BYTES + row * 128 + pch * 16, gB);        \
        }                                                                      \
        asm volatile("cp.async.commit_group;");                                \
    } while (0)

    LOAD_STAGE(0, 0);
    LOAD_STAGE(1, 1);

    for (int kt = 0; kt < nk; ++kt) {
        const int st = kt % NSTAGE;
        if (kt + 1 < nk) {
            asm volatile("cp.async.wait_group 1;");
        } else {
            asm volatile("cp.async.wait_group 0;");
        }
        __syncthreads();
        if (kt + 2 < nk) LOAD_STAGE(kt + 2, (kt + 2) % NSTAGE);

        const uint32_t aBase = sA + st * A_BYTES;
        const uint32_t bBase = sB + st * B_BYTES;
#pragma unroll
        for (int ks = 0; ks < 4; ++ks) {
            uint32_t af[4][4];
#pragma unroll
            for (int mt = 0; mt < 4; ++mt) {
                int row = warp_m + mt * 16 + (lane & 7) + ((lane >> 3) & 1) * 8;
                int ch  = ks * 2 + (lane >> 4);
                uint32_t ad = aBase + row * 128 + ((ch ^ (row & 7)) * 16);
                LDSM_X4(af[mt], ad);
            }
#pragma unroll
            for (int ng = 0; ng < 4; ++ng) {
                int nrow = warp_n + ng * 16 + (lane & 7) + ((lane >> 4) & 1) * 8;
                int ch   = ks * 2 + ((lane >> 3) & 1);
                uint32_t bd = bBase + nrow * 128 + ((ch ^ (nrow & 7)) * 16);
                uint32_t bf[4];
                LDSM_X4(bf, bd);
#pragma unroll
                for (int mt = 0; mt < 4; ++mt) {
                    MMA16816(acc[mt][ng * 2],     af[mt], bf[0], bf[1]);
                    MMA16816(acc[mt][ng * 2 + 1], af[mt], bf[2], bf[3]);
                }
            }
        }
        __syncthreads();
    }

    // epilogue
#pragma unroll
    for (int mt = 0; mt < 4; ++mt) {
        const int r0 = bm + warp_m + mt * 16 + (lane >> 2);
#pragma unroll
        for (int nt = 0; nt < 8; ++nt) {
            const int c = bn + warp_n + nt * 8 + (lane & 3) * 2;
            if (OUT_HALF) {
                __half* C = (__half*)Cv + blockIdx.z * csplit;
                __half2 v0 = __floats2half2_rn(acc[mt][nt][0] * alpha,
                                               acc[mt][nt][1] * alpha);
                __half2 v1 = __floats2half2_rn(acc[mt][nt][2] * alpha,
                                               acc[mt][nt][3] * alpha);
                *(__half2*)(C + (size_t)r0 * ldc + c)       = v0;
                *(__half2*)(C + (size_t)(r0 + 8) * ldc + c) = v1;
            } else {
                float* C = (float*)Cv + blockIdx.z * csplit;
                float2 v0 = make_float2(acc[mt][nt][0] * alpha, acc[mt][nt][1] * alpha);
                float2 v1 = make_float2(acc[mt][nt][2] * alpha, acc[mt][nt][3] * alpha);
                *(float2*)(C + (size_t)r0 * ldc + c)       = v0;
                *(float2*)(C + (size_t)(r0 + 8) * ldc + c) = v1;
            }
        }
    }
#undef LOAD_STAGE
}

// ---------------- plain fp32 -> fp16 conversion ------------------------------
__device__ __forceinline__ uint32_t pack2(__half a, __half b) {
    __half2 h = __halves2half2(a, b);
    return *(uint32_t*)&h;
}

__global__ void __launch_bounds__(256)
conv_h(const float* __restrict__ src, __half* __restrict__ dst, size_t n)
{
    const size_t n4 = n / 4;
    for (size_t i = (size_t)blockIdx.x * 256 + threadIdx.x; i < n4;
         i += (size_t)gridDim.x * 256) {
        float4 v = *(const float4*)(src + i * 4);
        uint2 u = make_uint2(
            pack2(__float2half_rn(v.x), __float2half_rn(v.y)),
            pack2(__float2half_rn(v.z), __float2half_rn(v.w)));
        *(uint2*)(dst + i * 4) = u;
    }
}

// fp16 transpose with src row stride: src[R x C, stride srcld] -> dst[C x R]
__global__ void __launch_bounds__(256)
trans_half(const __half* __restrict__ src, __half* __restrict__ dst,
           int R, int C, int srcld)
{
    __shared__ __half t[32][33];
    const int tx = threadIdx.x & 31, ty = threadIdx.x >> 5;
    const int bx = blockIdx.x, by = blockIdx.y;
#pragma unroll
    for (int j = 0; j < 32; j += 8)
        t[ty + j][tx] = src[(size_t)(by * 32 + ty + j) * srcld + bx * 32 + tx];
    __syncthreads();
#pragma unroll
    for (int j = 0; j < 32; j += 8)
        dst[(size_t)(bx * 32 + ty + j) * R + by * 32 + tx] = t[tx][ty + j];
}

// ---------------- softmax over S rows, emitting plain fp16 P ----------------
__global__ void __launch_bounds__(256)
softmax_h(const float* __restrict__ S, __half* __restrict__ P)
{
    __shared__ float buf[SEQ];
    __shared__ float red[256];
    const size_t base = (size_t)blockIdx.x * SEQ;
    const int tid = threadIdx.x;

    float lmax = -INFINITY;
    for (int i = tid; i < SEQ / 4; i += 256) {
        float4 v = *(const float4*)(S + base + (size_t)i * 4);
        *(float4*)&buf[i * 4] = v;
        lmax = fmaxf(lmax, fmaxf(fmaxf(v.x, v.y), fmaxf(v.z, v.w)));
    }
    red[tid] = lmax;
    __syncthreads();
#pragma unroll
    for (int s = 128; s > 0; s >>= 1) {
        if (tid < s) red[tid] = fmaxf(red[tid], red[tid + s]);
        __syncthreads();
    }
    const float m = red[0];
    __syncthreads();

    float lsum = 0.f;
    for (int i = tid; i < SEQ / 4; i += 256) {
        float4 v = *(const float4*)&buf[i * 4];
        v.x = __expf(v.x - m); v.y = __expf(v.y - m);
        v.z = __expf(v.z - m); v.w = __expf(v.w - m);
        *(float4*)&buf[i * 4] = v;
        lsum += v.x + v.y + v.z + v.w;
    }
    red[tid] = lsum;
    __syncthreads();
#pragma unroll
    for (int s = 128; s > 0; s >>= 1) {
        if (tid < s) red[tid] += red[tid + s];
        __syncthreads();
    }
    const float inv = 1.f / red[0];
    __syncthreads();

    __half* d = P + base;
    for (int i = tid; i < SEQ / 4; i += 256) {
        float4 v = *(const float4*)&buf[i * 4];
        uint2 u = make_uint2(
            pack2(__float2half_rn(v.x * inv), __float2half_rn(v.y * inv)),
            pack2(__float2half_rn(v.z * inv), __float2half_rn(v.w * inv)));
        *(uint2*)(d + i * 4) = u;
    }
}

// ---------------- split-K reduction: O = sum of 4 partials -------------------
__global__ void __launch_bounds__(256)
add4_f32(const float* __restrict__ a0, const float* __restrict__ a1,
         const float* __restrict__ a2, const float* __restrict__ a3,
         float* __restrict__ o, size_t n)
{
    const size_t n4 = n / 4;
    for (size_t i = (size_t)blockIdx.x * 256 + threadIdx.x; i < n4;
         i += (size_t)gridDim.x * 256) {
        float4 x = *(const float4*)(a0 + i * 4);
        float4 y = *(const float4*)(a1 + i * 4);
        float4 z = *(const float4*)(a2 + i * 4);
        float4 w = *(const float4*)(a3 + i * 4);
        x.x += y.x; x.y += y.y; x.z += y.z; x.w += y.w;
        z.x += w.x; z.y += w.y; z.z += w.z; z.w += w.w;
        x.x += z.x; x.y += z.y; x.z += z.z; x.w += z.w;
        *(float4*)(o + i * 4) = x;
    }
}

// ---------------------------------------------------------------------------
extern "C" void kernel_launch(void* const* d_in, const int* in_sizes, int n_in,
                              void* d_out, int out_size)
{
    const float* X  = (const float*)d_in[0];
    const float* Wq = (const float*)d_in[1];
    const float* Wk = (const float*)d_in[2];
    const float* Wv = (const float*)d_in[3];
    float* O = (float*)d_out;

    __half *X16, *Wc16, *QKV, *V16t, *P16;
    float *S, *Op;
    cudaGetSymbolAddress((void**)&X16,  g_X16);
    cudaGetSymbolAddress((void**)&Wc16, g_Wc16);
    cudaGetSymbolAddress((void**)&QKV,  g_QKV);
    cudaGetSymbolAddress((void**)&V16t, g_V16t);
    cudaGetSymbolAddress((void**)&S,    g_S);
    cudaGetSymbolAddress((void**)&P16,  g_P16);
    cudaGetSymbolAddress((void**)&Op,   g_Opart);

    cudaFuncSetAttribute(gemm_f16_mma<0>,
                         cudaFuncAttributeMaxDynamicSharedMemorySize, GEMM_SMEM);
    cudaFuncSetAttribute(gemm_f16_mma<1>,
                         cudaFuncAttributeMaxDynamicSharedMemorySize, GEMM_SMEM);

    const float inv_sqrt_d = 0.03608439182435161f;  // 1/sqrt(768)
    const dim3 blk(256);
    const size_t WSZ = (size_t)DIM * DIM;
    const size_t OSZ = (size_t)SEQ * DIM;

    // plain fp16 conversions; W concatenated [Wq;Wk;Wv] -> [2304 x 768]
    conv_h<<<592, blk>>>(X,  X16, (size_t)SEQ * DIM);
    conv_h<<<296, blk>>>(Wq, Wc16,           WSZ);
    conv_h<<<296, blk>>>(Wk, Wc16 + WSZ,     WSZ);
    conv_h<<<296, blk>>>(Wv, Wc16 + 2 * WSZ, WSZ);

    // fused projection: QKV[8192 x 2304] = X @ Wc^T  (576 CTAs)
    gemm_f16_mma<1><<<dim3(DIM3 / BN, SEQ / BM, 1), blk, GEMM_SMEM>>>(
        X16, Wc16, QKV, DIM3, DIM, DIM, DIM, DIM3, 1.f, 0);

    // S = (Q @ K^T) / sqrt(d): Q/K are strided slices of QKV  (2048 CTAs)
    gemm_f16_mma<0><<<dim3(SEQ / BN, SEQ / BM, 1), blk, GEMM_SMEM>>>(
        QKV, QKV + DIM, S, SEQ, DIM, DIM3, DIM3, SEQ, inv_sqrt_d, 0);

    // V transpose (strided slice of QKV) -> V16t [768 x 8192]
    trans_half<<<dim3(DIM / 32, SEQ / 32), blk>>>(QKV + 2 * DIM, V16t,
                                                  SEQ, DIM, DIM3);

    // softmax -> plain fp16 P
    softmax_h<<<SEQ, blk>>>(S, P16);

    // O = P @ V: split-K=4 via gridDim.z (768 CTAs)
    gemm_f16_mma<0><<<dim3(DIM / BN, SEQ / BM, 4), blk, GEMM_SMEM>>>(
        P16, V16t, Op, DIM, SEQ / 4, SEQ, SEQ, DIM, 1.f, OSZ);

    // O = sum of 4 partials
    add4_f32<<<1024, blk>>>(Op, Op + OSZ, Op + 2 * OSZ, Op + 3 * OSZ, O, OSZ);
}

// round 8
// speedup vs baseline: 1.1365x; 1.1365x over previous
#include <cuda_runtime.h>
#include <cuda_fp16.h>
#include <math.h>
#include <stdint.h>

#define SEQ 8192
#define DIM 768
#define DIM3 (3 * DIM)   // 2304

// ---------------- scratch (__device__ globals; no allocations allowed) -----
__device__ __align__(128) __half g_X16 [(size_t)SEQ * DIM];
__device__ __align__(128) __half g_Wc16[(size_t)DIM3 * DIM];       // [Wq;Wk;Wv]
__device__ __align__(128) __half g_QKV [(size_t)SEQ * DIM3];       // packed Q|K|V
__device__ __align__(128) __half g_V16t[(size_t)DIM * SEQ];
__device__ __align__(128) __half g_S16 [(size_t)SEQ * SEQ];        // fp16 scores / P in place
__device__ __align__(128) float  g_Opart[2][(size_t)SEQ * DIM];    // PV split-K partials

// ---------------- helpers ----------------------------------------------------
__device__ __forceinline__ uint32_t smem_u32(const void* p) {
    uint32_t a;
    asm("{ .reg .u64 t; cvta.to.shared.u64 t, %1; cvt.u32.u64 %0, t; }"
        : "=r"(a) : "l"(p));
    return a;
}

#define MMA16816(d, a, b0, b1)                                                 \
    asm volatile(                                                              \
        "mma.sync.aligned.m16n8k16.row.col.f32.f16.f16.f32 "                   \
        "{%0,%1,%2,%3}, {%4,%5,%6,%7}, {%8,%9}, {%0,%1,%2,%3};"                \
        : "+f"((d)[0]), "+f"((d)[1]), "+f"((d)[2]), "+f"((d)[3])               \
        : "r"((a)[0]), "r"((a)[1]), "r"((a)[2]), "r"((a)[3]),                  \
          "r"(b0), "r"(b1))

#define LDSM_X4(r, addr)                                                       \
    asm volatile("ldmatrix.sync.aligned.m8n8.x4.shared.b16 {%0,%1,%2,%3}, [%4];" \
        : "=r"((r)[0]), "=r"((r)[1]), "=r"((r)[2]), "=r"((r)[3]) : "r"(addr))

#define CP_ASYNC16(saddr, gptr)                                                \
    asm volatile("cp.async.cg.shared.global [%0], [%1], 16;"                   \
        :: "r"(saddr), "l"(gptr))

// ---------------- GEMM: C[M,N] = alpha * A[M,*] * B[N,*]^T  (fp16 in)
// CTA tile 128x128, BK=64 halves, 8 warps each 32x64, 3-stage cp.async.
// Explicit row strides lda/ldb/ldc (elements). gridDim.z = K-splits: split z
// covers K range [z*Ke, (z+1)*Ke) and writes C + z*csplit.
// OUT_HALF: 0 -> fp32 C, 1 -> fp16 C.
#define BM 128
#define BN 128
#define BKH 64                     // halves per K tile (128 bytes per row)
#define TILE_BYTES (128 * 128)     // 16 KB per operand stage
#define NSTAGE 3
#define GEMM_SMEM (2 * NSTAGE * TILE_BYTES)   // 96 KB

template <int OUT_HALF>
__global__ void __launch_bounds__(256, 2)
gemm_f16_mma(const __half* __restrict__ A, const __half* __restrict__ B,
             void* __restrict__ Cv, int N, int Ke,
             int lda, int ldb, int ldc, float alpha, size_t csplit)
{
    extern __shared__ char smem[];
    const uint32_t sA = smem_u32(smem);                    // NSTAGE stages A
    const uint32_t sB = sA + NSTAGE * TILE_BYTES;          // NSTAGE stages B

    const int tid  = threadIdx.x;
    const int lane = tid & 31;
    const int wid  = tid >> 5;
    const int warp_m = (wid & 3) * 32;
    const int warp_n = (wid >> 2) * 64;
    const int bm = blockIdx.y * BM;
    const int bn = blockIdx.x * BN;
    const int koff = blockIdx.z * Ke;
    const int nk = Ke / BKH;

    float acc[2][8][4];
#pragma unroll
    for (int i = 0; i < 2; ++i)
#pragma unroll
        for (int j = 0; j < 8; ++j)
#pragma unroll
            for (int k = 0; k < 4; ++k) acc[i][j][k] = 0.f;

#define LOAD_STAGE(kt, st)                                                     \
    do {                                                                       \
        _Pragma("unroll")                                                      \
        for (int i = 0; i < 4; ++i) {                                          \
            int idx = tid + i * 256;                                           \
            int row = idx >> 3;                                                \
            int ch  = idx & 7;                                                 \
            int pch = ch ^ (row & 7);                                          \
            const __half* gA = A + (size_t)(bm + row) * lda + koff + (kt) * BKH + ch * 8; \
            CP_ASYNC16(sA + (st) * TILE_BYTES + row * 128 + pch * 16, gA);     \
            const __half* gB = B + (size_t)(bn + row) * ldb + koff + (kt) * BKH + ch * 8; \
            CP_ASYNC16(sB + (st) * TILE_BYTES + row * 128 + pch * 16, gB);     \
        }                                                                      \
        asm volatile("cp.async.commit_group;");                                \
    } while (0)

    LOAD_STAGE(0, 0);
    LOAD_STAGE(1, 1);

    for (int kt = 0; kt < nk; ++kt) {
        const int st = kt % NSTAGE;
        if (kt + 1 < nk) {
            asm volatile("cp.async.wait_group 1;");
        } else {
            asm volatile("cp.async.wait_group 0;");
        }
        // Single barrier per k-tile: also orders stage reuse (3-stage ring —
        // LOAD(kt+2) overwrites the stage computed at kt-1, and every warp has
        // passed this barrier only after finishing kt-1's compute).
        __syncthreads();
        if (kt + 2 < nk) LOAD_STAGE(kt + 2, (kt + 2) % NSTAGE);

        const uint32_t aBase = sA + st * TILE_BYTES;
        const uint32_t bBase = sB + st * TILE_BYTES;
#pragma unroll
        for (int ks = 0; ks < 4; ++ks) {
            uint32_t af[2][4];
#pragma unroll
            for (int mt = 0; mt < 2; ++mt) {
                int row = warp_m + mt * 16 + (lane & 7) + ((lane >> 3) & 1) * 8;
                int ch  = ks * 2 + (lane >> 4);
                uint32_t ad = aBase + row * 128 + ((ch ^ (row & 7)) * 16);
                LDSM_X4(af[mt], ad);
            }
#pragma unroll
            for (int ng = 0; ng < 4; ++ng) {
                int nrow = warp_n + ng * 16 + (lane & 7) + ((lane >> 4) & 1) * 8;
                int ch   = ks * 2 + ((lane >> 3) & 1);
                uint32_t bd = bBase + nrow * 128 + ((ch ^ (nrow & 7)) * 16);
                uint32_t bf[4];
                LDSM_X4(bf, bd);
#pragma unroll
                for (int mt = 0; mt < 2; ++mt) {
                    MMA16816(acc[mt][ng * 2],     af[mt], bf[0], bf[1]);
                    MMA16816(acc[mt][ng * 2 + 1], af[mt], bf[2], bf[3]);
                }
            }
        }
    }

    // epilogue
#pragma unroll
    for (int mt = 0; mt < 2; ++mt) {
        const int r0 = bm + warp_m + mt * 16 + (lane >> 2);
#pragma unroll
        for (int nt = 0; nt < 8; ++nt) {
            const int c = bn + warp_n + nt * 8 + (lane & 3) * 2;
            if (OUT_HALF) {
                __half* C = (__half*)Cv + blockIdx.z * csplit;
                __half2 v0 = __floats2half2_rn(acc[mt][nt][0] * alpha,
                                               acc[mt][nt][1] * alpha);
                __half2 v1 = __floats2half2_rn(acc[mt][nt][2] * alpha,
                                               acc[mt][nt][3] * alpha);
                *(__half2*)(C + (size_t)r0 * ldc + c)       = v0;
                *(__half2*)(C + (size_t)(r0 + 8) * ldc + c) = v1;
            } else {
                float* C = (float*)Cv + blockIdx.z * csplit;
                float2 v0 = make_float2(acc[mt][nt][0] * alpha, acc[mt][nt][1] * alpha);
                float2 v1 = make_float2(acc[mt][nt][2] * alpha, acc[mt][nt][3] * alpha);
                *(float2*)(C + (size_t)r0 * ldc + c)       = v0;
                *(float2*)(C + (size_t)(r0 + 8) * ldc + c) = v1;
            }
        }
    }
#undef LOAD_STAGE
}

// ---------------- plain fp32 -> fp16 conversion ------------------------------
__device__ __forceinline__ uint32_t pack2(__half a, __half b) {
    __half2 h = __halves2half2(a, b);
    return *(uint32_t*)&h;
}

__global__ void __launch_bounds__(256)
conv_h(const float* __restrict__ src, __half* __restrict__ dst, size_t n)
{
    const size_t n4 = n / 4;
    for (size_t i = (size_t)blockIdx.x * 256 + threadIdx.x; i < n4;
         i += (size_t)gridDim.x * 256) {
        float4 v = *(const float4*)(src + i * 4);
        uint2 u = make_uint2(
            pack2(__float2half_rn(v.x), __float2half_rn(v.y)),
            pack2(__float2half_rn(v.z), __float2half_rn(v.w)));
        *(uint2*)(dst + i * 4) = u;
    }
}

// fp16 transpose with src row stride: src[R x C, stride srcld] -> dst[C x R]
__global__ void __launch_bounds__(256)
trans_half(const __half* __restrict__ src, __half* __restrict__ dst,
           int R, int C, int srcld)
{
    __shared__ __half t[32][33];
    const int tx = threadIdx.x & 31, ty = threadIdx.x >> 5;
    const int bx = blockIdx.x, by = blockIdx.y;
#pragma unroll
    for (int j = 0; j < 32; j += 8)
        t[ty + j][tx] = src[(size_t)(by * 32 + ty + j) * srcld + bx * 32 + tx];
    __syncthreads();
#pragma unroll
    for (int j = 0; j < 32; j += 8)
        dst[(size_t)(bx * 32 + ty + j) * R + by * 32 + tx] = t[tx][ty + j];
}

// ---------------- softmax over fp16 S rows, in-place fp16 P -----------------
__global__ void __launch_bounds__(256)
softmax_h16(__half* __restrict__ S)
{
    __shared__ float buf[SEQ];      // fp32 working row (32 KB)
    __shared__ float red[256];
    const size_t base = (size_t)blockIdx.x * SEQ;
    const int tid = threadIdx.x;

    float lmax = -INFINITY;
    for (int i = tid; i < SEQ / 8; i += 256) {
        uint4 u = *(const uint4*)(S + base + (size_t)i * 8);
        float2 f0 = __half22float2(*(__half2*)&u.x);
        float2 f1 = __half22float2(*(__half2*)&u.y);
        float2 f2 = __half22float2(*(__half2*)&u.z);
        float2 f3 = __half22float2(*(__half2*)&u.w);
        buf[i * 8 + 0] = f0.x; buf[i * 8 + 1] = f0.y;
        buf[i * 8 + 2] = f1.x; buf[i * 8 + 3] = f1.y;
        buf[i * 8 + 4] = f2.x; buf[i * 8 + 5] = f2.y;
        buf[i * 8 + 6] = f3.x; buf[i * 8 + 7] = f3.y;
        lmax = fmaxf(lmax, fmaxf(fmaxf(f0.x, f0.y), fmaxf(f1.x, f1.y)));
        lmax = fmaxf(lmax, fmaxf(fmaxf(f2.x, f2.y), fmaxf(f3.x, f3.y)));
    }
    red[tid] = lmax;
    __syncthreads();
#pragma unroll
    for (int s = 128; s > 0; s >>= 1) {
        if (tid < s) red[tid] = fmaxf(red[tid], red[tid + s]);
        __syncthreads();
    }
    const float m = red[0];
    __syncthreads();

    float lsum = 0.f;
    for (int i = tid; i < SEQ / 4; i += 256) {
        float4 v = *(const float4*)&buf[i * 4];
        v.x = __expf(v.x - m); v.y = __expf(v.y - m);
        v.z = __expf(v.z - m); v.w = __expf(v.w - m);
        *(float4*)&buf[i * 4] = v;
        lsum += v.x + v.y + v.z + v.w;
    }
    red[tid] = lsum;
    __syncthreads();
#pragma unroll
    for (int s = 128; s > 0; s >>= 1) {
        if (tid < s) red[tid] += red[tid + s];
        __syncthreads();
    }
    const float inv = 1.f / red[0];
    __syncthreads();

    __half* d = S + base;   // in place
    for (int i = tid; i < SEQ / 4; i += 256) {
        float4 v = *(const float4*)&buf[i * 4];
        uint2 u = make_uint2(
            pack2(__float2half_rn(v.x * inv), __float2half_rn(v.y * inv)),
            pack2(__float2half_rn(v.z * inv), __float2half_rn(v.w * inv)));
        *(uint2*)(d + i * 4) = u;
    }
}

// ---------------- split-K reduction: O = A0 + A1 -----------------------------
__global__ void __launch_bounds__(256)
add2_f32(const float* __restrict__ a, const float* __restrict__ b,
         float* __restrict__ o, size_t n)
{
    const size_t n4 = n / 4;
    for (size_t i = (size_t)blockIdx.x * 256 + threadIdx.x; i < n4;
         i += (size_t)gridDim.x * 256) {
        float4 x = *(const float4*)(a + i * 4);
        float4 y = *(const float4*)(b + i * 4);
        x.x += y.x; x.y += y.y; x.z += y.z; x.w += y.w;
        *(float4*)(o + i * 4) = x;
    }
}

// ---------------------------------------------------------------------------
extern "C" void kernel_launch(void* const* d_in, const int* in_sizes, int n_in,
                              void* d_out, int out_size)
{
    const float* X  = (const float*)d_in[0];
    const float* Wq = (const float*)d_in[1];
    const float* Wk = (const float*)d_in[2];
    const float* Wv = (const float*)d_in[3];
    float* O = (float*)d_out;

    __half *X16, *Wc16, *QKV, *V16t, *S16;
    float *Op;
    cudaGetSymbolAddress((void**)&X16,  g_X16);
    cudaGetSymbolAddress((void**)&Wc16, g_Wc16);
    cudaGetSymbolAddress((void**)&QKV,  g_QKV);
    cudaGetSymbolAddress((void**)&V16t, g_V16t);
    cudaGetSymbolAddress((void**)&S16,  g_S16);
    cudaGetSymbolAddress((void**)&Op,   g_Opart);

    cudaFuncSetAttribute(gemm_f16_mma<0>,
                         cudaFuncAttributeMaxDynamicSharedMemorySize, GEMM_SMEM);
    cudaFuncSetAttribute(gemm_f16_mma<1>,
                         cudaFuncAttributeMaxDynamicSharedMemorySize, GEMM_SMEM);

    const float inv_sqrt_d = 0.03608439182435161f;  // 1/sqrt(768)
    const dim3 blk(256);
    const size_t WSZ = (size_t)DIM * DIM;
    const size_t OSZ = (size_t)SEQ * DIM;

    // plain fp16 conversions; W concatenated [Wq;Wk;Wv] -> [2304 x 768]
    conv_h<<<592, blk>>>(X,  X16, (size_t)SEQ * DIM);
    conv_h<<<296, blk>>>(Wq, Wc16,           WSZ);
    conv_h<<<296, blk>>>(Wk, Wc16 + WSZ,     WSZ);
    conv_h<<<296, blk>>>(Wv, Wc16 + 2 * WSZ, WSZ);

    // fused projection: QKV[8192 x 2304] = X @ Wc^T  (1152 CTAs)
    gemm_f16_mma<1><<<dim3(DIM3 / BN, SEQ / BM, 1), blk, GEMM_SMEM>>>(
        X16, Wc16, QKV, DIM3, DIM, DIM, DIM, DIM3, 1.f, 0);

    // S = (Q @ K^T) / sqrt(d): fp16 scores (4096 CTAs)
    gemm_f16_mma<1><<<dim3(SEQ / BN, SEQ / BM, 1), blk, GEMM_SMEM>>>(
        QKV, QKV + DIM, S16, SEQ, DIM, DIM3, DIM3, SEQ, inv_sqrt_d, 0);

    // V transpose (strided slice of QKV) -> V16t [768 x 8192]
    trans_half<<<dim3(DIM / 32, SEQ / 32), blk>>>(QKV + 2 * DIM, V16t,
                                                  SEQ, DIM, DIM3);

    // softmax in place: S16 -> P (fp16)
    softmax_h16<<<SEQ, blk>>>(S16);

    // O = P @ V: split-K=2 via gridDim.z (768 CTAs)
    gemm_f16_mma<0><<<dim3(DIM / BN, SEQ / BM, 2), blk, GEMM_SMEM>>>(
        S16, V16t, Op, DIM, SEQ / 2, SEQ, SEQ, DIM, 1.f, OSZ);

    // O = partial0 + partial1
    add2_f32<<<1024, blk>>>(Op, Op + OSZ, O, OSZ);
}

// round 9
// speedup vs baseline: 1.2483x; 1.0984x over previous
#include <cuda_runtime.h>
#include <cuda_fp16.h>
#include <math.h>
#include <stdint.h>

#define SEQ 8192
#define DIM 768
#define DIM3 (3 * DIM)   // 2304

// ---------------- scratch (__device__ globals; no allocations allowed) -----
__device__ __align__(128) __half g_X16 [(size_t)SEQ * DIM];
__device__ __align__(128) __half g_Wc16[(size_t)DIM3 * DIM];       // [Wq;Wk;Wv]
__device__ __align__(128) __half g_QKV [(size_t)SEQ * DIM3];       // packed Q|K|V
__device__ __align__(128) __half g_V16t[(size_t)DIM * SEQ];
__device__ __align__(128) __half g_E16 [(size_t)SEQ * SEQ];        // exp(scores), fp16
__device__ __align__(128) float  g_rowsum[SEQ];                    // per-row exp sums
__device__ __align__(128) float  g_Opart[2][(size_t)SEQ * DIM];    // PV split-K partials

// ---------------- helpers ----------------------------------------------------
__device__ __forceinline__ uint32_t smem_u32(const void* p) {
    uint32_t a;
    asm("{ .reg .u64 t; cvta.to.shared.u64 t, %1; cvt.u32.u64 %0, t; }"
        : "=r"(a) : "l"(p));
    return a;
}

#define MMA16816(d, a, b0, b1)                                                 \
    asm volatile(                                                              \
        "mma.sync.aligned.m16n8k16.row.col.f32.f16.f16.f32 "                   \
        "{%0,%1,%2,%3}, {%4,%5,%6,%7}, {%8,%9}, {%0,%1,%2,%3};"                \
        : "+f"((d)[0]), "+f"((d)[1]), "+f"((d)[2]), "+f"((d)[3])               \
        : "r"((a)[0]), "r"((a)[1]), "r"((a)[2]), "r"((a)[3]),                  \
          "r"(b0), "r"(b1))

#define LDSM_X4(r, addr)                                                       \
    asm volatile("ldmatrix.sync.aligned.m8n8.x4.shared.b16 {%0,%1,%2,%3}, [%4];" \
        : "=r"((r)[0]), "=r"((r)[1]), "=r"((r)[2]), "=r"((r)[3]) : "r"(addr))

#define CP_ASYNC16(saddr, gptr)                                                \
    asm volatile("cp.async.cg.shared.global [%0], [%1], 16;"                   \
        :: "r"(saddr), "l"(gptr))

// ---------------- GEMM: C[M,N] = alpha * A[M,*] * B[N,*]^T  (fp16 in)
// CTA tile 128x128, BK=64 halves, 8 warps each 32x64, 3-stage cp.async.
// Explicit row strides lda/ldb/ldc (elements). gridDim.z = K-splits: split z
// covers K range [z*Ke, (z+1)*Ke) and writes C + z*csplit.
// MODE: 0 -> fp32 C;  1 -> fp16 C;
//       2 -> fp16 exp(alpha*acc) C + per-row atomic sum into rowsum[].
#define BM 128
#define BN 128
#define BKH 64                     // halves per K tile (128 bytes per row)
#define TILE_BYTES (128 * 128)     // 16 KB per operand stage
#define NSTAGE 3
#define GEMM_SMEM (2 * NSTAGE * TILE_BYTES)   // 96 KB

template <int MODE>
__global__ void __launch_bounds__(256, 2)
gemm_f16_mma(const __half* __restrict__ A, const __half* __restrict__ B,
             void* __restrict__ Cv, int N, int Ke,
             int lda, int ldb, int ldc, float alpha, size_t csplit,
             float* __restrict__ rowsum)
{
    extern __shared__ char smem[];
    const uint32_t sA = smem_u32(smem);                    // NSTAGE stages A
    const uint32_t sB = sA + NSTAGE * TILE_BYTES;          // NSTAGE stages B

    const int tid  = threadIdx.x;
    const int lane = tid & 31;
    const int wid  = tid >> 5;
    const int warp_m = (wid & 3) * 32;
    const int warp_n = (wid >> 2) * 64;
    const int bm = blockIdx.y * BM;
    const int bn = blockIdx.x * BN;
    const int koff = blockIdx.z * Ke;
    const int nk = Ke / BKH;

    float acc[2][8][4];
#pragma unroll
    for (int i = 0; i < 2; ++i)
#pragma unroll
        for (int j = 0; j < 8; ++j)
#pragma unroll
            for (int k = 0; k < 4; ++k) acc[i][j][k] = 0.f;

#define LOAD_STAGE(kt, st)                                                     \
    do {                                                                       \
        _Pragma("unroll")                                                      \
        for (int i = 0; i < 4; ++i) {                                          \
            int idx = tid + i * 256;                                           \
            int row = idx >> 3;                                                \
            int ch  = idx & 7;                                                 \
            int pch = ch ^ (row & 7);                                          \
            const __half* gA = A + (size_t)(bm + row) * lda + koff + (kt) * BKH + ch * 8; \
            CP_ASYNC16(sA + (st) * TILE_BYTES + row * 128 + pch * 16, gA);     \
            const __half* gB = B + (size_t)(bn + row) * ldb + koff + (kt) * BKH + ch * 8; \
            CP_ASYNC16(sB + (st) * TILE_BYTES + row * 128 + pch * 16, gB);     \
        }                                                                      \
        asm volatile("cp.async.commit_group;");                                \
    } while (0)

    LOAD_STAGE(0, 0);
    LOAD_STAGE(1, 1);

    for (int kt = 0; kt < nk; ++kt) {
        const int st = kt % NSTAGE;
        if (kt + 1 < nk) {
            asm volatile("cp.async.wait_group 1;");
        } else {
            asm volatile("cp.async.wait_group 0;");
        }
        // Single barrier per k-tile (3-stage ring orders stage reuse).
        __syncthreads();
        if (kt + 2 < nk) LOAD_STAGE(kt + 2, (kt + 2) % NSTAGE);

        const uint32_t aBase = sA + st * TILE_BYTES;
        const uint32_t bBase = sB + st * TILE_BYTES;
#pragma unroll
        for (int ks = 0; ks < 4; ++ks) {
            uint32_t af[2][4];
#pragma unroll
            for (int mt = 0; mt < 2; ++mt) {
                int row = warp_m + mt * 16 + (lane & 7) + ((lane >> 3) & 1) * 8;
                int ch  = ks * 2 + (lane >> 4);
                uint32_t ad = aBase + row * 128 + ((ch ^ (row & 7)) * 16);
                LDSM_X4(af[mt], ad);
            }
#pragma unroll
            for (int ng = 0; ng < 4; ++ng) {
                int nrow = warp_n + ng * 16 + (lane & 7) + ((lane >> 4) & 1) * 8;
                int ch   = ks * 2 + ((lane >> 3) & 1);
                uint32_t bd = bBase + nrow * 128 + ((ch ^ (nrow & 7)) * 16);
                uint32_t bf[4];
                LDSM_X4(bf, bd);
#pragma unroll
                for (int mt = 0; mt < 2; ++mt) {
                    MMA16816(acc[mt][ng * 2],     af[mt], bf[0], bf[1]);
                    MMA16816(acc[mt][ng * 2 + 1], af[mt], bf[2], bf[3]);
                }
            }
        }
    }

    // epilogue
    float lsum[2][2] = {{0.f, 0.f}, {0.f, 0.f}};
#pragma unroll
    for (int mt = 0; mt < 2; ++mt) {
        const int r0 = bm + warp_m + mt * 16 + (lane >> 2);
#pragma unroll
        for (int nt = 0; nt < 8; ++nt) {
            const int c = bn + warp_n + nt * 8 + (lane & 3) * 2;
            if (MODE == 2) {
                __half* C = (__half*)Cv;
                float e0 = __expf(acc[mt][nt][0] * alpha);
                float e1 = __expf(acc[mt][nt][1] * alpha);
                float e2 = __expf(acc[mt][nt][2] * alpha);
                float e3 = __expf(acc[mt][nt][3] * alpha);
                lsum[mt][0] += e0 + e1;
                lsum[mt][1] += e2 + e3;
                *(__half2*)(C + (size_t)r0 * ldc + c)       = __floats2half2_rn(e0, e1);
                *(__half2*)(C + (size_t)(r0 + 8) * ldc + c) = __floats2half2_rn(e2, e3);
            } else if (MODE == 1) {
                __half* C = (__half*)Cv + blockIdx.z * csplit;
                __half2 v0 = __floats2half2_rn(acc[mt][nt][0] * alpha,
                                               acc[mt][nt][1] * alpha);
                __half2 v1 = __floats2half2_rn(acc[mt][nt][2] * alpha,
                                               acc[mt][nt][3] * alpha);
                *(__half2*)(C + (size_t)r0 * ldc + c)       = v0;
                *(__half2*)(C + (size_t)(r0 + 8) * ldc + c) = v1;
            } else {
                float* C = (float*)Cv + blockIdx.z * csplit;
                float2 v0 = make_float2(acc[mt][nt][0] * alpha, acc[mt][nt][1] * alpha);
                float2 v1 = make_float2(acc[mt][nt][2] * alpha, acc[mt][nt][3] * alpha);
                *(float2*)(C + (size_t)r0 * ldc + c)       = v0;
                *(float2*)(C + (size_t)(r0 + 8) * ldc + c) = v1;
            }
        }
    }
    if (MODE == 2) {
        // 4 lanes (lane&3) share each row: butterfly-reduce, leader atomicAdd.
#pragma unroll
        for (int mt = 0; mt < 2; ++mt) {
#pragma unroll
            for (int h = 0; h < 2; ++h) {
                float s = lsum[mt][h];
                s += __shfl_xor_sync(0xffffffffu, s, 1);
                s += __shfl_xor_sync(0xffffffffu, s, 2);
                if ((lane & 3) == 0) {
                    int row = bm + warp_m + mt * 16 + (lane >> 2) + h * 8;
                    atomicAdd(rowsum + row, s);
                }
            }
        }
    }
#undef LOAD_STAGE
}

// ---------------- plain fp32 -> fp16 conversion ------------------------------
__device__ __forceinline__ uint32_t pack2(__half a, __half b) {
    __half2 h = __halves2half2(a, b);
    return *(uint32_t*)&h;
}

// X conversion; also zeroes rowsum (runs before the QK GEMM).
__global__ void __launch_bounds__(256)
conv_h_zero(const float* __restrict__ src, __half* __restrict__ dst, size_t n,
            float* __restrict__ rowsum)
{
    const size_t gtid = (size_t)blockIdx.x * 256 + threadIdx.x;
    if (gtid < SEQ) rowsum[gtid] = 0.f;
    const size_t n4 = n / 4;
    for (size_t i = gtid; i < n4; i += (size_t)gridDim.x * 256) {
        float4 v = *(const float4*)(src + i * 4);
        uint2 u = make_uint2(
            pack2(__float2half_rn(v.x), __float2half_rn(v.y)),
            pack2(__float2half_rn(v.z), __float2half_rn(v.w)));
        *(uint2*)(dst + i * 4) = u;
    }
}

__global__ void __launch_bounds__(256)
conv_h(const float* __restrict__ src, __half* __restrict__ dst, size_t n)
{
    const size_t n4 = n / 4;
    for (size_t i = (size_t)blockIdx.x * 256 + threadIdx.x; i < n4;
         i += (size_t)gridDim.x * 256) {
        float4 v = *(const float4*)(src + i * 4);
        uint2 u = make_uint2(
            pack2(__float2half_rn(v.x), __float2half_rn(v.y)),
            pack2(__float2half_rn(v.z), __float2half_rn(v.w)));
        *(uint2*)(dst + i * 4) = u;
    }
}

// fp16 transpose with src row stride: src[R x C, stride srcld] -> dst[C x R]
__global__ void __launch_bounds__(256)
trans_half(const __half* __restrict__ src, __half* __restrict__ dst,
           int R, int C, int srcld)
{
    __shared__ __half t[32][33];
    const int tx = threadIdx.x & 31, ty = threadIdx.x >> 5;
    const int bx = blockIdx.x, by = blockIdx.y;
#pragma unroll
    for (int j = 0; j < 32; j += 8)
        t[ty + j][tx] = src[(size_t)(by * 32 + ty + j) * srcld + bx * 32 + tx];
    __syncthreads();
#pragma unroll
    for (int j = 0; j < 32; j += 8)
        dst[(size_t)(bx * 32 + ty + j) * R + by * 32 + tx] = t[tx][ty + j];
}

// ---------------- split-K reduction + softmax normalization ------------------
// O[i] = (a[i] + b[i]) / rowsum[i / DIM]
__global__ void __launch_bounds__(256)
add2_scale(const float* __restrict__ a, const float* __restrict__ b,
           const float* __restrict__ rowsum, float* __restrict__ o, size_t n)
{
    const size_t n4 = n / 4;
    for (size_t i = (size_t)blockIdx.x * 256 + threadIdx.x; i < n4;
         i += (size_t)gridDim.x * 256) {
        float4 x = *(const float4*)(a + i * 4);
        float4 y = *(const float4*)(b + i * 4);
        const int row = (int)((i * 4) / DIM);
        const float inv = __frcp_rn(rowsum[row]);
        x.x = (x.x + y.x) * inv;
        x.y = (x.y + y.y) * inv;
        x.z = (x.z + y.z) * inv;
        x.w = (x.w + y.w) * inv;
        *(float4*)(o + i * 4) = x;
    }
}

// ---------------------------------------------------------------------------
extern "C" void kernel_launch(void* const* d_in, const int* in_sizes, int n_in,
                              void* d_out, int out_size)
{
    const float* X  = (const float*)d_in[0];
    const float* Wq = (const float*)d_in[1];
    const float* Wk = (const float*)d_in[2];
    const float* Wv = (const float*)d_in[3];
    float* O = (float*)d_out;

    __half *X16, *Wc16, *QKV, *V16t, *E16;
    float *Op, *rowsum;
    cudaGetSymbolAddress((void**)&X16,    g_X16);
    cudaGetSymbolAddress((void**)&Wc16,   g_Wc16);
    cudaGetSymbolAddress((void**)&QKV,    g_QKV);
    cudaGetSymbolAddress((void**)&V16t,   g_V16t);
    cudaGetSymbolAddress((void**)&E16,    g_E16);
    cudaGetSymbolAddress((void**)&rowsum, g_rowsum);
    cudaGetSymbolAddress((void**)&Op,     g_Opart);

    cudaFuncSetAttribute(gemm_f16_mma<0>,
                         cudaFuncAttributeMaxDynamicSharedMemorySize, GEMM_SMEM);
    cudaFuncSetAttribute(gemm_f16_mma<1>,
                         cudaFuncAttributeMaxDynamicSharedMemorySize, GEMM_SMEM);
    cudaFuncSetAttribute(gemm_f16_mma<2>,
                         cudaFuncAttributeMaxDynamicSharedMemorySize, GEMM_SMEM);

    const float inv_sqrt_d = 0.03608439182435161f;  // 1/sqrt(768)
    const dim3 blk(256);
    const size_t WSZ = (size_t)DIM * DIM;
    const size_t OSZ = (size_t)SEQ * DIM;

    // fp16 conversions; X conv also zeroes rowsum
    conv_h_zero<<<592, blk>>>(X, X16, (size_t)SEQ * DIM, rowsum);
    conv_h<<<296, blk>>>(Wq, Wc16,           WSZ);
    conv_h<<<296, blk>>>(Wk, Wc16 + WSZ,     WSZ);
    conv_h<<<296, blk>>>(Wv, Wc16 + 2 * WSZ, WSZ);

    // fused projection: QKV[8192 x 2304] = X @ Wc^T
    gemm_f16_mma<1><<<dim3(DIM3 / BN, SEQ / BM, 1), blk, GEMM_SMEM>>>(
        X16, Wc16, QKV, DIM3, DIM, DIM, DIM, DIM3, 1.f, 0, nullptr);

    // E = exp((Q @ K^T) / sqrt(d)), fp16; per-row sums accumulated atomically
    gemm_f16_mma<2><<<dim3(SEQ / BN, SEQ / BM, 1), blk, GEMM_SMEM>>>(
        QKV, QKV + DIM, E16, SEQ, DIM, DIM3, DIM3, SEQ, inv_sqrt_d, 0, rowsum);

    // V transpose (strided slice of QKV) -> V16t [768 x 8192]
    trans_half<<<dim3(DIM / 32, SEQ / 32), blk>>>(QKV + 2 * DIM, V16t,
                                                  SEQ, DIM, DIM3);

    // O' = E @ V: split-K=2 via gridDim.z
    gemm_f16_mma<0><<<dim3(DIM / BN, SEQ / BM, 2), blk, GEMM_SMEM>>>(
        E16, V16t, Op, DIM, SEQ / 2, SEQ, SEQ, DIM, 1.f, OSZ, nullptr);

    // O = (partial0 + partial1) / rowsum[row]
    add2_scale<<<1024, blk>>>(Op, Op + OSZ, rowsum, O, OSZ);
}